// round 5
// baseline (speedup 1.0000x reference)
#include <cuda_runtime.h>
#include <cuda_bf16.h>
#include <cstdint>

// Problem constants
#define B_     32
#define IN_CH  16
#define OUT_CH 16
#define KK     3
#define DIL    4
#define COND   8
#define T_OUT  65536
#define PADW   (DIL * (KK - 1))      // 8
#define T_IN   (T_OUT + PADW)        // 65544
#define WSZ    (IN_CH * KK * OUT_CH) // 768

// Tile geometry: 128 tiles of 512 timesteps per batch (256 pairs per tile).
#define TILE_T   512
#define TILE_P   (TILE_T / 2)        // 256 pairs
#define ROW_P    260                 // pairs per channel row (256 + 4 tap pad)
#define ROW_BYTES (ROW_P * 8)        // 2080, multiple of 16
#define CPS      2                   // channels per pipeline stage
#define NSTAGES  (IN_CH / CPS)       // 8
#define NBUF     3                   // triple buffer, issue depth 2

// Per-batch hypernet weights, duplicated as {w,w} in 64 bits so one shared
// load yields the packed B operand of fma.rn.f32x2.
__device__ ulonglong2 g_w[B_ * WSZ / 2];

// ---------------------------------------------------------------------------
// Kernel 1: hypernetwork.  grid=B_, block=WSZ threads.
// ---------------------------------------------------------------------------
__global__ void hyper_kernel(const float* __restrict__ p,
                             const float* __restrict__ W1,
                             const float* __restrict__ b1,
                             const float* __restrict__ W2,
                             const float* __restrict__ b2) {
    const int b = blockIdx.x;
    const int j = threadIdx.x;           // 0..767
    __shared__ float h[IN_CH];

    if (j < IN_CH) {
        float s = b1[j];
#pragma unroll
        for (int k = 0; k < COND; k++)
            s += p[b * COND + k] * W1[k * IN_CH + j];
        h[j] = (s > 0.0f) ? s : 0.2f * s;
    }
    __syncthreads();

    float s = b2[j];
#pragma unroll
    for (int c = 0; c < IN_CH; c++)
        s += h[c] * W2[c * WSZ + j];

    float2* w2out = reinterpret_cast<float2*>(g_w);
    w2out[b * WSZ + j] = make_float2(s, s);
}

// ---------------------------------------------------------------------------
// PTX helpers
// ---------------------------------------------------------------------------
__device__ __forceinline__ void fma2(unsigned long long& d,
                                     unsigned long long a,
                                     unsigned long long b) {
    asm volatile("fma.rn.f32x2 %0, %1, %2, %0;" : "+l"(d) : "l"(a), "l"(b));
}

__device__ __forceinline__ uint32_t smem_u32(const void* ptr) {
    uint32_t a;
    asm("{ .reg .u64 t; cvta.to.shared.u64 t, %1; cvt.u32.u64 %0, t; }"
        : "=r"(a) : "l"(ptr));
    return a;
}

__device__ __forceinline__ void mbar_init(uint32_t mbar, uint32_t count) {
    asm volatile("mbarrier.init.shared.b64 [%0], %1;" :: "r"(mbar), "r"(count)
                 : "memory");
}

__device__ __forceinline__ void mbar_expect_tx(uint32_t mbar, uint32_t bytes) {
    asm volatile("mbarrier.arrive.expect_tx.shared.b64 _, [%0], %1;"
                 :: "r"(mbar), "r"(bytes) : "memory");
}

__device__ __forceinline__ void bulk_g2s(uint32_t dst, const void* src,
                                         uint32_t bytes, uint32_t mbar) {
    asm volatile(
        "cp.async.bulk.shared::cta.global.mbarrier::complete_tx::bytes "
        "[%0], [%1], %2, [%3];"
        :: "r"(dst), "l"(src), "r"(bytes), "r"(mbar) : "memory");
}

__device__ __forceinline__ void mbar_wait(uint32_t mbar, uint32_t parity) {
    asm volatile(
        "{\n\t"
        ".reg .pred P;\n\t"
        "WAIT_%=:\n\t"
        "mbarrier.try_wait.parity.acquire.cta.shared::cta.b64 P, [%0], %1, 0x989680;\n\t"
        "@P bra.uni DONE_%=;\n\t"
        "bra.uni WAIT_%=;\n\t"
        "DONE_%=:\n\t"
        "}"
        :: "r"(mbar), "r"(parity) : "memory");
}

// ---------------------------------------------------------------------------
// Kernel 2: main conv, triple-buffered cp.async.bulk pipeline (R3 protocol),
// re-dimensioned for 4 CTAs/SM (32 warps):
//   grid  = (128, 32), block = (128, 2), <=64 regs target
//   tx -> 2 strided output pairs (stride 128), ty -> half of 16 out channels.
// ---------------------------------------------------------------------------
__global__ __launch_bounds__(256, 4)
void conv_kernel(const float* __restrict__ x, float* __restrict__ y) {
    const int b   = blockIdx.y;
    const int tx  = threadIdx.x;                 // 0..127
    const int oh  = threadIdx.y;                 // 0..1
    const int tid = oh * 128 + tx;               // 0..255

    __shared__ __align__(16) unsigned long long xs[NBUF][CPS][ROW_P];
    __shared__ ulonglong2 ws[WSZ / 2];           // 6KB duplicated weights
    __shared__ __align__(8) unsigned long long mbar_store[NBUF];

    // Cooperative weight load (visible after the init __syncthreads).
#pragma unroll
    for (int k = tid; k < WSZ / 2; k += 256)
        ws[k] = g_w[b * (WSZ / 2) + k];

    const uint32_t mbar0 = smem_u32(&mbar_store[0]);
    if (tid == 0) {
#pragma unroll
        for (int i = 0; i < NBUF; i++)
            mbar_init(mbar0 + 8u * i, 1);
    }
    __syncthreads();

    // Per-channel gmem source rows for this tile.
    const float* xbase = x + (size_t)(b * IN_CH) * T_IN + blockIdx.x * TILE_T;

    // Prologue: issue stages 0 and 1.
    if (tid == 0) {
#pragma unroll
        for (int s = 0; s < 2; s++) {
            const uint32_t mb = mbar0 + 8u * s;
            mbar_expect_tx(mb, CPS * ROW_BYTES);
#pragma unroll
            for (int r = 0; r < CPS; r++)
                bulk_g2s(smem_u32(&xs[s][r][0]),
                         xbase + (size_t)(s * CPS + r) * T_IN, ROW_BYTES, mb);
        }
    }

    unsigned long long acc[2][8];                // [pair j][out ch in half]
#pragma unroll
    for (int j = 0; j < 2; j++)
#pragma unroll
        for (int op = 0; op < 8; op++)
            acc[j][op] = 0ULL;

#pragma unroll 1
    for (int s = 0; s < NSTAGES; s++) {
        const int buf = s % NBUF;
        mbar_wait(mbar0 + 8u * buf, (s / NBUF) & 1);
        __syncthreads();   // all threads done with stage s-1 -> buffer free

        if (s + 2 < NSTAGES && tid == 0) {
            const int t  = s + 2;
            const int tb = t % NBUF;
            const uint32_t mb = mbar0 + 8u * tb;
            mbar_expect_tx(mb, CPS * ROW_BYTES);
#pragma unroll
            for (int r = 0; r < CPS; r++)
                bulk_g2s(smem_u32(&xs[tb][r][0]),
                         xbase + (size_t)(t * CPS + r) * T_IN, ROW_BYTES, mb);
        }

#pragma unroll
        for (int cc = 0; cc < CPS; cc++) {
            const int c = s * CPS + cc;
            const unsigned long long* xr = &xs[buf][cc][tx];

            // 6 conflict-free LDS.64: tap i at pair offset (4 - 2i)
            unsigned long long xv[2][3];
#pragma unroll
            for (int j = 0; j < 2; j++)
#pragma unroll
                for (int i = 0; i < 3; i++)
                    xv[j][i] = xr[128 * j + 4 - 2 * i];

            const ulonglong2* wrow = &ws[(c * OUT_CH + oh * 8) / 2];
#pragma unroll
            for (int i = 0; i < 3; i++) {
                const ulonglong2* wt = wrow + i * (IN_CH * OUT_CH / 2);
#pragma unroll
                for (int m = 0; m < 4; m++) {
                    const ulonglong2 w = wt[m];      // broadcast LDS.128
#pragma unroll
                    for (int j = 0; j < 2; j++) {
                        fma2(acc[j][2 * m + 0], xv[j][i], w.x);
                        fma2(acc[j][2 * m + 1], xv[j][i], w.y);
                    }
                }
            }
        }
    }

    // Store: y[b][oh*8+op][...], coalesced STG.64
    const int p0 = blockIdx.x * TILE_P + tx;
    unsigned long long* yb =
        reinterpret_cast<unsigned long long*>(y + (size_t)(b * OUT_CH + oh * 8) * T_OUT) + p0;
    const int yrowp = T_OUT / 2;
#pragma unroll
    for (int op = 0; op < 8; op++) {
        unsigned long long* yo = yb + op * yrowp;
#pragma unroll
        for (int j = 0; j < 2; j++)
            yo[128 * j] = acc[j][op];
    }
}

// ---------------------------------------------------------------------------
extern "C" void kernel_launch(void* const* d_in, const int* in_sizes, int n_in,
                              void* d_out, int out_size) {
    const float* x  = (const float*)d_in[0];
    const float* p  = (const float*)d_in[1];
    const float* W1 = (const float*)d_in[2];
    const float* b1 = (const float*)d_in[3];
    const float* W2 = (const float*)d_in[4];
    const float* b2 = (const float*)d_in[5];
    float* y = (float*)d_out;

    hyper_kernel<<<B_, WSZ>>>(p, W1, b1, W2, b2);

    dim3 grid(T_OUT / TILE_T, B_);
    dim3 block(128, 2);
    conv_kernel<<<grid, block>>>(x, y);
}